// round 14
// baseline (speedup 1.0000x reference)
#include <cuda_runtime.h>
#include <cuda_bf16.h>
#include <math.h>
#include <stdint.h>

#define TOK   6272
#define DIMN  768
#define NHEAD 12
#define DHEAD 64
#define MLPN  3072
#define KCENT 64
#define SEQ   196
#define DEPTH 4
#define KMIT  10
#define QKVN  2304
#define NPART 64
#define NASS  (TOK/64)

// ---------------- scratch ----------------
__device__ float g_x[TOK*DIMN];
__device__ float g_qkv[TOK*QKVN];
__device__ float g_centers[KCENT*DIMN];
__device__ int   g_labels[TOK];
__device__ int   g_cntp[NASS*KCENT];
__device__ float g_part[NPART*KCENT*DIMN];
__device__ float g_cproj[KCENT*DIMN];

__device__ __nv_bfloat16 g_ah[TOK*DIMN];
__device__ __nv_bfloat16 g_al[TOK*DIMN];
__device__ __nv_bfloat16 g_gh[TOK*MLPN];
__device__ __nv_bfloat16 g_gl[TOK*MLPN];

__device__ __nv_bfloat16 g_wqkvh[DEPTH*QKVN*DIMN], g_wqkvl[DEPTH*QKVN*DIMN];
__device__ __nv_bfloat16 g_woh[DEPTH*DIMN*DIMN],   g_wol[DEPTH*DIMN*DIMN];
__device__ __nv_bfloat16 g_w1h[DEPTH*DIMN*MLPN],   g_w1l[DEPTH*DIMN*MLPN];
__device__ __nv_bfloat16 g_w2h[DEPTH*MLPN*DIMN],   g_w2l[DEPTH*MLPN*DIMN];

// ================= PTX helpers =================
__device__ __forceinline__ uint32_t smem_u32(const void* p) {
    uint32_t a;
    asm("{ .reg .u64 t; cvta.to.shared.u64 t, %1; cvt.u32.u64 %0, t; }"
        : "=r"(a) : "l"(p));
    return a;
}
__device__ __forceinline__ void ldm_x4(uint32_t& r0, uint32_t& r1,
                                       uint32_t& r2, uint32_t& r3, uint32_t addr) {
    asm volatile("ldmatrix.sync.aligned.m8n8.x4.shared.b16 {%0,%1,%2,%3}, [%4];"
                 : "=r"(r0), "=r"(r1), "=r"(r2), "=r"(r3) : "r"(addr));
}
__device__ __forceinline__ void mma_bf16(float* c, const uint32_t* a, const uint32_t* b) {
    asm volatile(
        "mma.sync.aligned.m16n8k16.row.col.f32.bf16.bf16.f32 "
        "{%0,%1,%2,%3}, {%4,%5,%6,%7}, {%8,%9}, {%0,%1,%2,%3};"
        : "+f"(c[0]), "+f"(c[1]), "+f"(c[2]), "+f"(c[3])
        : "r"(a[0]), "r"(a[1]), "r"(a[2]), "r"(a[3]), "r"(b[0]), "r"(b[1]));
}
__device__ __forceinline__ void cp16(uint32_t dst, const void* src) {
    asm volatile("cp.async.cg.shared.global [%0], [%1], 16;" :: "r"(dst), "l"(src));
}
__device__ __forceinline__ void cp_commit() {
    asm volatile("cp.async.commit_group;" ::: "memory");
}
__device__ __forceinline__ void split_bf16(float v, __nv_bfloat16& h, __nv_bfloat16& l) {
    h = __float2bfloat16(v);
    l = __float2bfloat16(v - __bfloat162float(h));
}

// ================= input copy =================
__global__ __launch_bounds__(256) void copy_kernel(const float4* __restrict__ src,
                                                   float4* __restrict__ dst, int n4)
{
    int i = blockIdx.x * 256 + threadIdx.x;
    if (i < n4) dst[i] = src[i];
}

// ================= weight transpose + split =================
__device__ __forceinline__ void conv_tile(const float* __restrict__ W,
    __nv_bfloat16* __restrict__ hi, __nv_bfloat16* __restrict__ lo,
    int K, int N, int n0, int k0)
{
    __shared__ float t[32][33];
    int tx = threadIdx.x & 31, ty = threadIdx.x >> 5;
    #pragma unroll
    for (int i = 0; i < 4; i++)
        t[ty + 8*i][tx] = W[(size_t)(k0 + ty + 8*i) * N + n0 + tx];
    __syncthreads();
    #pragma unroll
    for (int i = 0; i < 4; i++) {
        int rr = ty + 8*i;
        float v = t[tx][rr];
        __nv_bfloat16 h, l;
        split_bf16(v, h, l);
        size_t idx = (size_t)(n0 + rr) * K + k0 + tx;
        hi[idx] = h;
        lo[idx] = l;
    }
}

__global__ __launch_bounds__(256) void conv_sq(
    const float* __restrict__ wq, const float* __restrict__ wk,
    const float* __restrict__ wv, const float* __restrict__ wo,
    __nv_bfloat16* __restrict__ qkvh, __nv_bfloat16* __restrict__ qkvl,
    __nv_bfloat16* __restrict__ oh,   __nv_bfloat16* __restrict__ ol)
{
    int z = blockIdx.z;
    int d = z >> 2, m = z & 3;
    size_t osq = (size_t)DIMN*DIMN;
    const float* src = (m == 0) ? wq : (m == 1) ? wk : (m == 2) ? wv : wo;
    src += (size_t)d * osq;
    __nv_bfloat16 *dh, *dl;
    if (m < 3) {
        dh = qkvh + (size_t)d*QKVN*DIMN + (size_t)m*osq;
        dl = qkvl + (size_t)d*QKVN*DIMN + (size_t)m*osq;
    } else {
        dh = oh + (size_t)d*osq;
        dl = ol + (size_t)d*osq;
    }
    conv_tile(src, dh, dl, DIMN, DIMN, blockIdx.x*32, blockIdx.y*32);
}

__global__ __launch_bounds__(256) void conv_w1(const float* __restrict__ w1,
    __nv_bfloat16* __restrict__ hi, __nv_bfloat16* __restrict__ lo)
{
    size_t om = (size_t)blockIdx.z * DIMN * MLPN;
    conv_tile(w1 + om, hi + om, lo + om, DIMN, MLPN, blockIdx.x*32, blockIdx.y*32);
}
__global__ __launch_bounds__(256) void conv_w2(const float* __restrict__ w2,
    __nv_bfloat16* __restrict__ hi, __nv_bfloat16* __restrict__ lo)
{
    size_t om = (size_t)blockIdx.z * DIMN * MLPN;
    conv_tile(w2 + om, hi + om, lo + om, MLPN, DIMN, blockIdx.x*32, blockIdx.y*32);
}

// ================= HMMA split-bf16 GEMM =================
#define TGB 40960
#define TG_SMEM (2*TGB)

template <int EPI>
__global__ __launch_bounds__(256, 2) void tgemm(
    int M, int N, int K,
    const __nv_bfloat16* __restrict__ Ahi, const __nv_bfloat16* __restrict__ Alo,
    const __nv_bfloat16* __restrict__ Bhi, const __nv_bfloat16* __restrict__ Blo,
    const float* __restrict__ bias, const float* __restrict__ res,
    float* __restrict__ C,
    __nv_bfloat16* __restrict__ Ohi, __nv_bfloat16* __restrict__ Olo)
{
    extern __shared__ char smc[];
    uint32_t sb = smem_u32(smc);

    int tid = threadIdx.x;
    int wid = tid >> 5, lane = tid & 31;
    int wm = wid & 3, wn = wid >> 2;
    int bm = blockIdx.y * 128, bn = blockIdx.x * 128;

    const __nv_bfloat16* Abase_h = Ahi + (size_t)bm * K;
    const __nv_bfloat16* Abase_l = Alo + (size_t)bm * K;
    const __nv_bfloat16* Bbase_h = Bhi + (size_t)bn * K;
    const __nv_bfloat16* Bbase_l = Blo + (size_t)bn * K;

    int nchunk = K >> 5;

    int r0 = tid >> 2, seg0 = tid & 3;
    int r1 = r0 + 64;
    uint32_t s0 = (uint32_t)(r0 * 80 + seg0 * 16);
    uint32_t s1 = (uint32_t)(r1 * 80 + seg0 * 16);

    float acc[2][8][4];
    #pragma unroll
    for (int i = 0; i < 2; i++)
        #pragma unroll
        for (int j = 0; j < 8; j++)
            #pragma unroll
            for (int q = 0; q < 4; q++) acc[i][j][q] = 0.f;

    {
        uint32_t tb = sb;
        size_t g0 = (size_t)r0 * K + seg0 * 8;
        size_t g1 = (size_t)r1 * K + seg0 * 8;
        cp16(tb +         s0, Abase_h + g0); cp16(tb +         s1, Abase_h + g1);
        cp16(tb + 10240 + s0, Abase_l + g0); cp16(tb + 10240 + s1, Abase_l + g1);
        cp16(tb + 20480 + s0, Bbase_h + g0); cp16(tb + 20480 + s1, Bbase_h + g1);
        cp16(tb + 30720 + s0, Bbase_l + g0); cp16(tb + 30720 + s1, Bbase_l + g1);
        cp_commit();
    }

    int a_row = wm * 32 + (lane & 15);
    int a_colx = (lane >> 4) * 8;
    int b_row = wn * 64 + (lane & 7) + ((lane >> 4) * 8);
    int b_colx = ((lane >> 3) & 1) * 8;

    for (int c = 0; c < nchunk; c++) {
        asm volatile("cp.async.wait_group 0;" ::: "memory");
        __syncthreads();

        uint32_t tb = sb + (c & 1) * TGB;

        uint32_t ah[2][4], al[2][4];
        #pragma unroll
        for (int ma = 0; ma < 2; ma++) {
            uint32_t ad = tb + (uint32_t)((a_row + ma*16) * 80 + a_colx * 2);
            ldm_x4(ah[ma][0], ah[ma][1], ah[ma][2], ah[ma][3], ad);
            ldm_x4(al[ma][0], al[ma][1], al[ma][2], al[ma][3], ad + 10240);
        }
        {
            uint32_t bh[8][2];
            #pragma unroll
            for (int na2 = 0; na2 < 4; na2++) {
                uint32_t bd = tb + 20480 +
                    (uint32_t)((b_row + na2*16) * 80 + b_colx * 2);
                ldm_x4(bh[2*na2][0], bh[2*na2][1], bh[2*na2+1][0], bh[2*na2+1][1], bd);
            }
            #pragma unroll
            for (int ma = 0; ma < 2; ma++)
                #pragma unroll
                for (int na = 0; na < 8; na++)
                    mma_bf16(acc[ma][na], ah[ma], bh[na]);

            if (c + 1 < nchunk) {
                uint32_t pb = sb + ((c + 1) & 1) * TGB;
                int k0 = (c + 1) << 5;
                size_t g0 = (size_t)r0 * K + k0 + seg0 * 8;
                size_t g1 = (size_t)r1 * K + k0 + seg0 * 8;
                cp16(pb +         s0, Abase_h + g0); cp16(pb +         s1, Abase_h + g1);
                cp16(pb + 10240 + s0, Abase_l + g0); cp16(pb + 10240 + s1, Abase_l + g1);
                cp16(pb + 20480 + s0, Bbase_h + g0); cp16(pb + 20480 + s1, Bbase_h + g1);
                cp16(pb + 30720 + s0, Bbase_l + g0); cp16(pb + 30720 + s1, Bbase_l + g1);
                cp_commit();
            }

            #pragma unroll
            for (int ma = 0; ma < 2; ma++)
                #pragma unroll
                for (int na = 0; na < 8; na++)
                    mma_bf16(acc[ma][na], al[ma], bh[na]);
        }
        {
            uint32_t bl[8][2];
            #pragma unroll
            for (int na2 = 0; na2 < 4; na2++) {
                uint32_t bd = tb + 30720 +
                    (uint32_t)((b_row + na2*16) * 80 + b_colx * 2);
                ldm_x4(bl[2*na2][0], bl[2*na2][1], bl[2*na2+1][0], bl[2*na2+1][1], bd);
            }
            #pragma unroll
            for (int ma = 0; ma < 2; ma++)
                #pragma unroll
                for (int na = 0; na < 8; na++)
                    mma_bf16(acc[ma][na], ah[ma], bl[na]);
        }
        {
            int k = 16;
            #pragma unroll
            for (int ma = 0; ma < 2; ma++) {
                uint32_t ad = tb + (uint32_t)((a_row + ma*16) * 80 + (k + a_colx) * 2);
                ldm_x4(ah[ma][0], ah[ma][1], ah[ma][2], ah[ma][3], ad);
                ldm_x4(al[ma][0], al[ma][1], al[ma][2], al[ma][3], ad + 10240);
            }
            {
                uint32_t bh[8][2];
                #pragma unroll
                for (int na2 = 0; na2 < 4; na2++) {
                    uint32_t bd = tb + 20480 +
                        (uint32_t)((b_row + na2*16) * 80 + (k + b_colx) * 2);
                    ldm_x4(bh[2*na2][0], bh[2*na2][1], bh[2*na2+1][0], bh[2*na2+1][1], bd);
                }
                #pragma unroll
                for (int ma = 0; ma < 2; ma++)
                    #pragma unroll
                    for (int na = 0; na < 8; na++)
                        mma_bf16(acc[ma][na], ah[ma], bh[na]);
                #pragma unroll
                for (int ma = 0; ma < 2; ma++)
                    #pragma unroll
                    for (int na = 0; na < 8; na++)
                        mma_bf16(acc[ma][na], al[ma], bh[na]);
            }
            {
                uint32_t bl[8][2];
                #pragma unroll
                for (int na2 = 0; na2 < 4; na2++) {
                    uint32_t bd = tb + 30720 +
                        (uint32_t)((b_row + na2*16) * 80 + (k + b_colx) * 2);
                    ldm_x4(bl[2*na2][0], bl[2*na2][1], bl[2*na2+1][0], bl[2*na2+1][1], bd);
                }
                #pragma unroll
                for (int ma = 0; ma < 2; ma++)
                    #pragma unroll
                    for (int na = 0; na < 8; na++)
                        mma_bf16(acc[ma][na], ah[ma], bl[na]);
            }
        }
    }

    int gid = lane >> 2, tig = lane & 3;
    #pragma unroll
    for (int ma = 0; ma < 2; ma++) {
        #pragma unroll
        for (int half = 0; half < 2; half++) {
            int row = bm + wm*32 + ma*16 + gid + half*8;
            int colb = bn + wn*64;
            #pragma unroll
            for (int na = 0; na < 8; na++) {
                int cc = na*8 + tig*2;
                float v0 = acc[ma][na][half*2 + 0];
                float v1 = acc[ma][na][half*2 + 1];
                if (EPI == 0) {
                    *(float2*)(C + (size_t)row * N + colb + cc) = make_float2(v0, v1);
                } else if (EPI == 1) {
                    const float* rp = res + (size_t)row * N + colb;
                    v0 += bias[colb + cc]     + rp[cc];
                    v1 += bias[colb + cc + 1] + rp[cc + 1];
                    *(float2*)(C + (size_t)row * N + colb + cc) = make_float2(v0, v1);
                } else {
                    float u0 = v0 + bias[colb + cc];
                    float u1 = v1 + bias[colb + cc + 1];
                    v0 = 0.5f * u0 * (1.f + erff(u0 * 0.70710678118654752f));
                    v1 = 0.5f * u1 * (1.f + erff(u1 * 0.70710678118654752f));
                    __nv_bfloat16 h0, l0, h1, l1;
                    split_bf16(v0, h0, l0);
                    split_bf16(v1, h1, l1);
                    size_t oi = ((size_t)row * N + colb + cc) >> 1;
                    ((__nv_bfloat162*)Ohi)[oi] = __halves2bfloat162(h0, h1);
                    ((__nv_bfloat162*)Olo)[oi] = __halves2bfloat162(l0, l1);
                }
            }
        }
    }
}

// ---------------- LayerNorm (warp-per-row) ----------------
__global__ __launch_bounds__(256) void ln_split(const float* __restrict__ x,
    const float* __restrict__ w, const float* __restrict__ b,
    __nv_bfloat16* __restrict__ ohi, __nv_bfloat16* __restrict__ olo)
{
    int warp = threadIdx.x >> 5, lane = threadIdx.x & 31;
    int row = blockIdx.x * 8 + warp;
    const float* xr = x + (size_t)row * DIMN;

    float4 v[6];
    #pragma unroll
    for (int i = 0; i < 6; i++)
        v[i] = *(const float4*)(xr + (i*32 + lane)*4);

    float s = 0.f;
    #pragma unroll
    for (int i = 0; i < 6; i++) s += (v[i].x + v[i].y) + (v[i].z + v[i].w);
    #pragma unroll
    for (int o = 16; o; o >>= 1) s += __shfl_xor_sync(0xffffffffu, s, o);
    float mean = s * (1.f/768.f);

    float vs = 0.f;
    #pragma unroll
    for (int i = 0; i < 6; i++) {
        float d0 = v[i].x - mean, d1 = v[i].y - mean;
        float d2 = v[i].z - mean, d3 = v[i].w - mean;
        vs += (d0*d0 + d1*d1) + (d2*d2 + d3*d3);
    }
    #pragma unroll
    for (int o = 16; o; o >>= 1) vs += __shfl_xor_sync(0xffffffffu, vs, o);
    float rs = rsqrtf(vs * (1.f/768.f) + 1e-5f);

    size_t ob = (size_t)row * DIMN;
    #pragma unroll
    for (int i = 0; i < 6; i++) {
        int col = (i*32 + lane)*4;
        float4 w4 = *(const float4*)(w + col);
        float4 b4 = *(const float4*)(b + col);
        float r0 = (v[i].x - mean) * rs * w4.x + b4.x;
        float r1 = (v[i].y - mean) * rs * w4.y + b4.y;
        float r2 = (v[i].z - mean) * rs * w4.z + b4.z;
        float r3 = (v[i].w - mean) * rs * w4.w + b4.w;
        __nv_bfloat16 h0, l0, h1, l1, h2, l2, h3, l3;
        split_bf16(r0, h0, l0); split_bf16(r1, h1, l1);
        split_bf16(r2, h2, l2); split_bf16(r3, h3, l3);
        size_t oi = (ob + col) >> 1;
        ((__nv_bfloat162*)ohi)[oi]   = __halves2bfloat162(h0, h1);
        ((__nv_bfloat162*)ohi)[oi+1] = __halves2bfloat162(h2, h3);
        ((__nv_bfloat162*)olo)[oi]   = __halves2bfloat162(l0, l1);
        ((__nv_bfloat162*)olo)[oi+1] = __halves2bfloat162(l2, l3);
    }
}

// ---------------- fused attention: 25 warps per (b,h) block ----------------
#define KSTR 68
#define AWRP 25
#define ATHR (AWRP*32)
#define ATT_SMEM ((SEQ*KSTR*2 + AWRP*4*64 + AWRP*4*224) * 4)

__global__ __launch_bounds__(ATHR) void attn_kernel(
    const float* __restrict__ QKV,
    __nv_bfloat16* __restrict__ Ohi, __nv_bfloat16* __restrict__ Olo)
{
    extern __shared__ float sm[];
    float* Ks = sm;
    float* Vs = Ks + SEQ*KSTR;
    float* qs = Vs + SEQ*KSTR;
    float* Ps = qs + AWRP*4*64;

    int bh = blockIdx.x;
    int bN = (bh / NHEAD) * SEQ;
    int h  = bh % NHEAD;
    size_t qbase = (size_t)bN * QKVN + h * DHEAD;

    for (int idx = threadIdx.x; idx < SEQ * DHEAD; idx += ATHR) {
        int r = idx >> 6, c = idx & 63;
        Ks[r*KSTR + c] = QKV[qbase + (size_t)r * QKVN + 768 + c];
        Vs[r*KSTR + c] = QKV[qbase + (size_t)r * QKVN + 1536 + c];
    }
    __syncthreads();

    int warp = threadIdx.x >> 5, lane = threadIdx.x & 31;
    float* qw = qs + warp * 256;
    float* pw = Ps + warp * 896;

    for (int g = warp; g < 49; g += AWRP) {
        int r0 = g * 4;
        for (int i = lane; i < 256; i += 32) {
            int rr = i >> 6, d = i & 63;
            qw[rr*64 + d] = QKV[qbase + (size_t)(r0 + rr) * QKVN + d];
        }
        __syncwarp();

        float s[4][7];
        #pragma unroll
        for (int r = 0; r < 4; r++)
            #pragma unroll
            for (int t = 0; t < 7; t++) s[r][t] = 0.f;

        #pragma unroll
        for (int d4 = 0; d4 < 16; d4++) {
            float4 q0 = *(float4*)(qw + 0*64 + d4*4);
            float4 q1 = *(float4*)(qw + 1*64 + d4*4);
            float4 q2 = *(float4*)(qw + 2*64 + d4*4);
            float4 q3 = *(float4*)(qw + 3*64 + d4*4);
            #pragma unroll
            for (int t = 0; t < 7; t++) {
                int j = lane + 32*t;
                if (j < SEQ) {
                    float4 k4 = *(float4*)(Ks + j*KSTR + d4*4);
                    s[0][t] += q0.x*k4.x + q0.y*k4.y + q0.z*k4.z + q0.w*k4.w;
                    s[1][t] += q1.x*k4.x + q1.y*k4.y + q1.z*k4.z + q1.w*k4.w;
                    s[2][t] += q2.x*k4.x + q2.y*k4.y + q2.z*k4.z + q2.w*k4.w;
                    s[3][t] += q3.x*k4.x + q3.y*k4.y + q3.z*k4.z + q3.w*k4.w;
                }
            }
        }

        #pragma unroll
        for (int r = 0; r < 4; r++) {
            float m = -1e30f;
            #pragma unroll
            for (int t = 0; t < 7; t++) {
                int j = lane + 32*t;
                float val = (j < SEQ) ? s[r][t] * 0.125f : -1e30f;
                s[r][t] = val;
                m = fmaxf(m, val);
            }
            #pragma unroll
            for (int o = 16; o; o >>= 1) m = fmaxf(m, __shfl_xor_sync(0xffffffffu, m, o));
            float sum = 0.f;
            #pragma unroll
            for (int t = 0; t < 7; t++) {
                int j = lane + 32*t;
                float e = (j < SEQ) ? __expf(s[r][t] - m) : 0.f;
                s[r][t] = e;
                sum += e;
            }
            #pragma unroll
            for (int o = 16; o; o >>= 1) sum += __shfl_xor_sync(0xffffffffu, sum, o);
            float inv = 1.f / sum;
            #pragma unroll
            for (int t = 0; t < 7; t++) {
                int j = lane + 32*t;
                pw[r*224 + j] = s[r][t] * inv;
            }
        }
        __syncwarp();

        float2 o0 = make_float2(0.f,0.f), o1 = o0, o2 = o0, o3 = o0;
        for (int jj = 0; jj < 49; jj++) {
            int j = jj * 4;
            float4 p0 = *(float4*)(pw + 0*224 + j);
            float4 p1 = *(float4*)(pw + 1*224 + j);
            float4 p2 = *(float4*)(pw + 2*224 + j);
            float4 p3 = *(float4*)(pw + 3*224 + j);
            float2 va = *(float2*)(Vs + (j+0)*KSTR + lane*2);
            float2 vb = *(float2*)(Vs + (j+1)*KSTR + lane*2);
            float2 vc = *(float2*)(Vs + (j+2)*KSTR + lane*2);
            float2 vd = *(float2*)(Vs + (j+3)*KSTR + lane*2);
            o0.x += p0.x*va.x; o0.y += p0.x*va.y;
            o0.x += p0.y*vb.x; o0.y += p0.y*vb.y;
            o0.x += p0.z*vc.x; o0.y += p0.z*vc.y;
            o0.x += p0.w*vd.x; o0.y += p0.w*vd.y;
            o1.x += p1.x*va.x; o1.y += p1.x*va.y;
            o1.x += p1.y*vb.x; o1.y += p1.y*vb.y;
            o1.x += p1.z*vc.x; o1.y += p1.z*vc.y;
            o1.x += p1.w*vd.x; o1.y += p1.w*vd.y;
            o2.x += p2.x*va.x; o2.y += p2.x*va.y;
            o2.x += p2.y*vb.x; o2.y += p2.y*vb.y;
            o2.x += p2.z*vc.x; o2.y += p2.z*vc.y;
            o2.x += p2.w*vd.x; o2.y += p2.w*vd.y;
            o3.x += p3.x*va.x; o3.y += p3.x*va.y;
            o3.x += p3.y*vb.x; o3.y += p3.y*vb.y;
            o3.x += p3.z*vc.x; o3.y += p3.z*vc.y;
            o3.x += p3.w*vd.x; o3.y += p3.w*vd.y;
        }
        #pragma unroll
        for (int r = 0; r < 4; r++) {
            float2 ov = (r == 0) ? o0 : (r == 1) ? o1 : (r == 2) ? o2 : o3;
            __nv_bfloat16 h0, l0, h1, l1;
            split_bf16(ov.x, h0, l0);
            split_bf16(ov.y, h1, l1);
            size_t oi = ((size_t)(bN + r0 + r) * DIMN + h * DHEAD + lane*2) >> 1;
            ((__nv_bfloat162*)Ohi)[oi] = __halves2bfloat162(h0, h1);
            ((__nv_bfloat162*)Olo)[oi] = __halves2bfloat162(l0, l1);
        }
        __syncwarp();
    }
}

// ---------------- k-means ----------------
__global__ __launch_bounds__(256) void assign_kernel(
    const float* __restrict__ X, const float* __restrict__ C,
    int* __restrict__ labels, int* __restrict__ cntp)
{
    __shared__ float Xs[64*65];
    __shared__ float Cs[64*65];
    __shared__ float cred[256];
    __shared__ float cnsh[64];
    __shared__ int   hist[64];
    int p0 = blockIdx.x * 64;
    int tid = threadIdx.x;

    {
        int row = tid & 63, q = tid >> 6;
        const float* cr = C + (size_t)row * DIMN + q * 192;
        float s = 0.f;
        #pragma unroll 4
        for (int k = 0; k < 192; k++) s += cr[k] * cr[k];
        cred[(q << 6) | row] = s;
    }
    if (tid < 64) hist[tid] = 0;
    __syncthreads();
    if (tid < 64)
        cnsh[tid] = (cred[tid] + cred[64 + tid]) + (cred[128 + tid] + cred[192 + tid]);

    int ty = tid >> 4, tx = tid & 15;
    float acc[4][4];
    #pragma unroll
    for (int i = 0; i < 4; i++)
        #pragma unroll
        for (int j = 0; j < 4; j++) acc[i][j] = 0.f;

    for (int k0 = 0; k0 < DIMN; k0 += 64) {
        __syncthreads();
        for (int idx = tid; idx < 4096; idx += 256) {
            int r = idx >> 6, d = idx & 63;
            Xs[r*65 + d] = X[(size_t)(p0 + r) * DIMN + k0 + d];
            Cs[r*65 + d] = C[(size_t)r * DIMN + k0 + d];
        }
        __syncthreads();
        for (int k = 0; k < 64; k++) {
            float a[4], b[4];
            #pragma unroll
            for (int i = 0; i < 4; i++) a[i] = Xs[(ty*4 + i)*65 + k];
            #pragma unroll
            for (int j = 0; j < 4; j++) b[j] = Cs[(tx*4 + j)*65 + k];
            #pragma unroll
            for (int i = 0; i < 4; i++)
                #pragma unroll
                for (int j = 0; j < 4; j++) acc[i][j] += a[i] * b[j];
        }
    }
    __syncthreads();
    #pragma unroll
    for (int i = 0; i < 4; i++)
        #pragma unroll
        for (int j = 0; j < 4; j++)
            Xs[(ty*4 + i)*64 + tx*4 + j] = cnsh[tx*4 + j] - 2.f * acc[i][j];
    __syncthreads();
    if (tid < 64) {
        int p = tid;
        float best = Xs[p*64]; int bi = 0;
        for (int c = 1; c < 64; c++) {
            float d = Xs[p*64 + c];
            if (d < best) { best = d; bi = c; }
        }
        labels[p0 + p] = bi;
        atomicAdd(&hist[bi], 1);
    }
    __syncthreads();
    if (tid < 64) cntp[blockIdx.x * 64 + tid] = hist[tid];
}

// 64 blocks x 768 threads; 1 column per thread -> 1 RMW per point
__global__ __launch_bounds__(768) void kmeans_partial(
    const float* __restrict__ X, const int* __restrict__ labels,
    float* __restrict__ partials)
{
    extern __shared__ float sacc[];
    for (int i = threadIdx.x; i < KCENT*DIMN; i += 768) sacc[i] = 0.f;
    __syncthreads();
    int p0 = blockIdx.x * (TOK/NPART);
    int t = threadIdx.x;
    for (int p = p0; p < p0 + (TOK/NPART); p++) {
        int l = labels[p];
        sacc[l * DIMN + t] += X[(size_t)p * DIMN + t];
    }
    __syncthreads();
    float* out = partials + (size_t)blockIdx.x * (KCENT*DIMN);
    for (int i = threadIdx.x; i < KCENT*DIMN; i += 768) out[i] = sacc[i];
}

__global__ __launch_bounds__(256) void kmeans_reduce(
    const float* __restrict__ partials, const int* __restrict__ cntp,
    float* __restrict__ centers)
{
    __shared__ float s_cnt;
    int idx = blockIdx.x * 256 + threadIdx.x;
    int row = idx / DIMN;
    if (threadIdx.x == 0) {
        int c = 0;
        for (int b = 0; b < NASS; b++) c += cntp[b * 64 + row];
        s_cnt = (float)c;
    }
    __syncthreads();
    float s = 0.f;
    #pragma unroll 4
    for (int b = 0; b < NPART; b++) s += partials[(size_t)b * (KCENT*DIMN) + idx];
    if (s_cnt > 0.f) centers[idx] = s / s_cnt;
}

__global__ __launch_bounds__(256) void cproj_kernel(
    const float* __restrict__ centers, const float* __restrict__ W,
    const float* __restrict__ bias, float* __restrict__ out)
{
    int idx = blockIdx.x * 256 + threadIdx.x;
    if (idx >= KCENT*DIMN) return;
    int r = idx / DIMN, c = idx - r * DIMN;
    const float* cr = centers + (size_t)r * DIMN;
    float acc = 0.f;
    #pragma unroll 4
    for (int k = 0; k < DIMN; k++) acc += cr[k] * W[(size_t)k * DIMN + c];
    out[idx] = acc + bias[c];
}

__global__ __launch_bounds__(256) void gather_kernel(
    const float* __restrict__ cproj, const int* __restrict__ labels,
    float* __restrict__ out)
{
    int idx = blockIdx.x * 256 + threadIdx.x;
    if (idx >= TOK*DIMN) return;
    int p = idx / DIMN, d = idx - p * DIMN;
    out[idx] = cproj[(size_t)labels[p] * DIMN + d];
}

// ---------------- host orchestration ----------------
extern "C" void kernel_launch(void* const* d_in, const int* in_sizes, int n_in,
                              void* d_out, int out_size)
{
    const float* in_x   = (const float*)d_in[0];
    const float* ln1_w  = (const float*)d_in[1];
    const float* ln1_b  = (const float*)d_in[2];
    const float* wq     = (const float*)d_in[3];
    const float* wk     = (const float*)d_in[4];
    const float* wv     = (const float*)d_in[5];
    const float* wo     = (const float*)d_in[6];
    const float* bo     = (const float*)d_in[7];
    const float* ln2_w  = (const float*)d_in[8];
    const float* ln2_b  = (const float*)d_in[9];
    const float* w1     = (const float*)d_in[10];
    const float* b1     = (const float*)d_in[11];
    const float* w2     = (const float*)d_in[12];
    const float* b2     = (const float*)d_in[13];
    const float* ct_w   = (const float*)d_in[14];
    const float* ct_b   = (const float*)d_in[15];

    float *px, *pqkv, *pcent, *ppart, *pcproj;
    int *plab, *pcntp;
    __nv_bfloat16 *pah, *pal, *pgh, *pgl,
                  *pwqkvh, *pwqkvl, *pwoh, *pwol, *pw1h, *pw1l, *pw2h, *pw2l;
    cudaGetSymbolAddress((void**)&px,    g_x);
    cudaGetSymbolAddress((void**)&pqkv,  g_qkv);
    cudaGetSymbolAddress((void**)&pcent, g_centers);
    cudaGetSymbolAddress((void**)&plab,  g_labels);
    cudaGetSymbolAddress((void**)&pcntp, g_cntp);
    cudaGetSymbolAddress((void**)&ppart, g_part);
    cudaGetSymbolAddress((void**)&pcproj,g_cproj);
    cudaGetSymbolAddress((void**)&pah,   g_ah);
    cudaGetSymbolAddress((void**)&pal,   g_al);
    cudaGetSymbolAddress((void**)&pgh,   g_gh);
    cudaGetSymbolAddress((void**)&pgl,   g_gl);
    cudaGetSymbolAddress((void**)&pwqkvh,g_wqkvh);
    cudaGetSymbolAddress((void**)&pwqkvl,g_wqkvl);
    cudaGetSymbolAddress((void**)&pwoh,  g_woh);
    cudaGetSymbolAddress((void**)&pwol,  g_wol);
    cudaGetSymbolAddress((void**)&pw1h,  g_w1h);
    cudaGetSymbolAddress((void**)&pw1l,  g_w1l);
    cudaGetSymbolAddress((void**)&pw2h,  g_w2h);
    cudaGetSymbolAddress((void**)&pw2l,  g_w2l);

    cudaFuncSetAttribute(attn_kernel, cudaFuncAttributeMaxDynamicSharedMemorySize, ATT_SMEM);
    cudaFuncSetAttribute(kmeans_partial, cudaFuncAttributeMaxDynamicSharedMemorySize,
                         KCENT*DIMN*(int)sizeof(float));
    cudaFuncSetAttribute(tgemm<0>, cudaFuncAttributeMaxDynamicSharedMemorySize, TG_SMEM);
    cudaFuncSetAttribute(tgemm<1>, cudaFuncAttributeMaxDynamicSharedMemorySize, TG_SMEM);
    cudaFuncSetAttribute(tgemm<2>, cudaFuncAttributeMaxDynamicSharedMemorySize, TG_SMEM);

    dim3 gQKV(QKVN/128, TOK/128);
    dim3 g768(DIMN/128, TOK/128);
    dim3 g3072(MLPN/128, TOK/128);

    // index 3 = attn_kernel (profiled)
    conv_sq<<<dim3(DIMN/32, DIMN/32, DEPTH*4), 256>>>(wq, wk, wv, wo,
        pwqkvh, pwqkvl, pwoh, pwol);                                                // 0
    ln_split<<<TOK/8, 256>>>(in_x, ln1_w, ln1_b, pah, pal);                         // 1
    tgemm<0><<<gQKV, 256, TG_SMEM>>>(TOK, QKVN, DIMN, pah, pal,
        pwqkvh, pwqkvl, nullptr, nullptr, pqkv, nullptr, nullptr);                  // 2
    attn_kernel<<<32*NHEAD, ATHR, ATT_SMEM>>>(pqkv, pah, pal);                      // 3 <- profiled
    copy_kernel<<<(TOK*DIMN/4 + 255)/256, 256>>>((const float4*)in_x, (float4*)px,
                                                 TOK*DIMN/4);                       // 4
    conv_w1<<<dim3(MLPN/32, DIMN/32, DEPTH), 256>>>(w1, pw1h, pw1l);                // 5
    conv_w2<<<dim3(DIMN/32, MLPN/32, DEPTH), 256>>>(w2, pw2h, pw2l);                // 6

    for (int d = 0; d < DEPTH; d++) {
        size_t oq  = (size_t)d*QKVN*DIMN;
        size_t osq = (size_t)DIMN*DIMN;
        size_t om  = (size_t)d*DIMN*MLPN;

        if (d > 0) {
            ln_split<<<TOK/8, 256>>>(px, ln1_w + d*DIMN, ln1_b + d*DIMN, pah, pal);
            tgemm<0><<<gQKV, 256, TG_SMEM>>>(TOK, QKVN, DIMN, pah, pal,
                pwqkvh + oq, pwqkvl + oq, nullptr, nullptr, pqkv, nullptr, nullptr);
            attn_kernel<<<32*NHEAD, ATHR, ATT_SMEM>>>(pqkv, pah, pal);
        }
        tgemm<1><<<g768, 256, TG_SMEM>>>(TOK, DIMN, DIMN, pah, pal,
            pwoh + (size_t)d*osq, pwol + (size_t)d*osq, bo + d*DIMN, px, px,
            nullptr, nullptr);
        ln_split<<<TOK/8, 256>>>(px, ln2_w + d*DIMN, ln2_b + d*DIMN, pah, pal);
        tgemm<2><<<g3072, 256, TG_SMEM>>>(TOK, MLPN, DIMN, pah, pal,
            pw1h + om, pw1l + om, b1 + d*MLPN, nullptr, nullptr, pgh, pgl);
        tgemm<1><<<g768, 256, TG_SMEM>>>(TOK, DIMN, MLPN, pgh, pgl,
            pw2h + om, pw2l + om, b2 + d*DIMN, px, px, nullptr, nullptr);
    }

    // ---- k-means ----
    cudaMemcpyAsync(pcent, px, (size_t)KCENT*DIMN*sizeof(float), cudaMemcpyDeviceToDevice, 0);
    for (int it = 0; it < KMIT; it++) {
        assign_kernel<<<NASS, 256>>>(px, pcent, plab, pcntp);
        kmeans_partial<<<NPART, 768, KCENT*DIMN*sizeof(float)>>>(px, plab, ppart);
        kmeans_reduce<<<KCENT*DIMN/256, 256>>>(ppart, pcntp, pcent);
    }
    assign_kernel<<<NASS, 256>>>(px, pcent, plab, pcntp);

    cproj_kernel<<<(KCENT*DIMN + 255)/256, 256>>>(pcent, ct_w, ct_b, pcproj);
    gather_kernel<<<(TOK*DIMN + 255)/256, 256>>>(pcproj, plab, (float*)d_out);
}

// round 15
// speedup vs baseline: 1.0205x; 1.0205x over previous
#include <cuda_runtime.h>
#include <cuda_bf16.h>
#include <math.h>
#include <stdint.h>

#define TOK   6272
#define DIMN  768
#define NHEAD 12
#define DHEAD 64
#define MLPN  3072
#define KCENT 64
#define SEQ   196
#define DEPTH 4
#define KMIT  10
#define QKVN  2304
#define NPART 64
#define NASS  (TOK/64)

// ---------------- scratch ----------------
__device__ float g_x[TOK*DIMN];
__device__ float g_qkv[TOK*QKVN];
__device__ float g_centers[KCENT*DIMN];
__device__ int   g_labels[TOK];
__device__ int   g_cntp[NASS*KCENT];
__device__ float g_part[NPART*KCENT*DIMN];
__device__ float g_cproj[KCENT*DIMN];

__device__ __nv_bfloat16 g_ah[TOK*DIMN];
__device__ __nv_bfloat16 g_al[TOK*DIMN];
__device__ __nv_bfloat16 g_gh[TOK*MLPN];
__device__ __nv_bfloat16 g_gl[TOK*MLPN];

__device__ __nv_bfloat16 g_wqkvh[DEPTH*QKVN*DIMN], g_wqkvl[DEPTH*QKVN*DIMN];
__device__ __nv_bfloat16 g_woh[DEPTH*DIMN*DIMN],   g_wol[DEPTH*DIMN*DIMN];
__device__ __nv_bfloat16 g_w1h[DEPTH*DIMN*MLPN],   g_w1l[DEPTH*DIMN*MLPN];
__device__ __nv_bfloat16 g_w2h[DEPTH*MLPN*DIMN],   g_w2l[DEPTH*MLPN*DIMN];

// ================= PTX helpers =================
__device__ __forceinline__ uint32_t smem_u32(const void* p) {
    uint32_t a;
    asm("{ .reg .u64 t; cvta.to.shared.u64 t, %1; cvt.u32.u64 %0, t; }"
        : "=r"(a) : "l"(p));
    return a;
}
__device__ __forceinline__ void ldm_x4(uint32_t& r0, uint32_t& r1,
                                       uint32_t& r2, uint32_t& r3, uint32_t addr) {
    asm volatile("ldmatrix.sync.aligned.m8n8.x4.shared.b16 {%0,%1,%2,%3}, [%4];"
                 : "=r"(r0), "=r"(r1), "=r"(r2), "=r"(r3) : "r"(addr));
}
__device__ __forceinline__ void mma_bf16(float* c, const uint32_t* a, const uint32_t* b) {
    asm volatile(
        "mma.sync.aligned.m16n8k16.row.col.f32.bf16.bf16.f32 "
        "{%0,%1,%2,%3}, {%4,%5,%6,%7}, {%8,%9}, {%0,%1,%2,%3};"
        : "+f"(c[0]), "+f"(c[1]), "+f"(c[2]), "+f"(c[3])
        : "r"(a[0]), "r"(a[1]), "r"(a[2]), "r"(a[3]), "r"(b[0]), "r"(b[1]));
}
__device__ __forceinline__ void cp16(uint32_t dst, const void* src) {
    asm volatile("cp.async.cg.shared.global [%0], [%1], 16;" :: "r"(dst), "l"(src));
}
__device__ __forceinline__ void cp_commit() {
    asm volatile("cp.async.commit_group;" ::: "memory");
}
__device__ __forceinline__ void split_bf16(float v, __nv_bfloat16& h, __nv_bfloat16& l) {
    h = __float2bfloat16(v);
    l = __float2bfloat16(v - __bfloat162float(h));
}

// ================= input copy =================
__global__ __launch_bounds__(256) void copy_kernel(const float4* __restrict__ src,
                                                   float4* __restrict__ dst, int n4)
{
    int i = blockIdx.x * 256 + threadIdx.x;
    if (i < n4) dst[i] = src[i];
}

// ================= weight transpose + split =================
__device__ __forceinline__ void conv_tile(const float* __restrict__ W,
    __nv_bfloat16* __restrict__ hi, __nv_bfloat16* __restrict__ lo,
    int K, int N, int n0, int k0)
{
    __shared__ float t[32][33];
    int tx = threadIdx.x & 31, ty = threadIdx.x >> 5;
    #pragma unroll
    for (int i = 0; i < 4; i++)
        t[ty + 8*i][tx] = W[(size_t)(k0 + ty + 8*i) * N + n0 + tx];
    __syncthreads();
    #pragma unroll
    for (int i = 0; i < 4; i++) {
        int rr = ty + 8*i;
        float v = t[tx][rr];
        __nv_bfloat16 h, l;
        split_bf16(v, h, l);
        size_t idx = (size_t)(n0 + rr) * K + k0 + tx;
        hi[idx] = h;
        lo[idx] = l;
    }
}

__global__ __launch_bounds__(256) void conv_sq(
    const float* __restrict__ wq, const float* __restrict__ wk,
    const float* __restrict__ wv, const float* __restrict__ wo,
    __nv_bfloat16* __restrict__ qkvh, __nv_bfloat16* __restrict__ qkvl,
    __nv_bfloat16* __restrict__ oh,   __nv_bfloat16* __restrict__ ol)
{
    int z = blockIdx.z;
    int d = z >> 2, m = z & 3;
    size_t osq = (size_t)DIMN*DIMN;
    const float* src = (m == 0) ? wq : (m == 1) ? wk : (m == 2) ? wv : wo;
    src += (size_t)d * osq;
    __nv_bfloat16 *dh, *dl;
    if (m < 3) {
        dh = qkvh + (size_t)d*QKVN*DIMN + (size_t)m*osq;
        dl = qkvl + (size_t)d*QKVN*DIMN + (size_t)m*osq;
    } else {
        dh = oh + (size_t)d*osq;
        dl = ol + (size_t)d*osq;
    }
    conv_tile(src, dh, dl, DIMN, DIMN, blockIdx.x*32, blockIdx.y*32);
}

__global__ __launch_bounds__(256) void conv_w1(const float* __restrict__ w1,
    __nv_bfloat16* __restrict__ hi, __nv_bfloat16* __restrict__ lo)
{
    size_t om = (size_t)blockIdx.z * DIMN * MLPN;
    conv_tile(w1 + om, hi + om, lo + om, DIMN, MLPN, blockIdx.x*32, blockIdx.y*32);
}
__global__ __launch_bounds__(256) void conv_w2(const float* __restrict__ w2,
    __nv_bfloat16* __restrict__ hi, __nv_bfloat16* __restrict__ lo)
{
    size_t om = (size_t)blockIdx.z * DIMN * MLPN;
    conv_tile(w2 + om, hi + om, lo + om, MLPN, DIMN, blockIdx.x*32, blockIdx.y*32);
}

// ================= HMMA split-bf16 GEMM =================
#define TGB 40960
#define TG_SMEM (2*TGB)

template <int EPI>
__global__ __launch_bounds__(256, 2) void tgemm(
    int M, int N, int K,
    const __nv_bfloat16* __restrict__ Ahi, const __nv_bfloat16* __restrict__ Alo,
    const __nv_bfloat16* __restrict__ Bhi, const __nv_bfloat16* __restrict__ Blo,
    const float* __restrict__ bias, const float* __restrict__ res,
    float* __restrict__ C,
    __nv_bfloat16* __restrict__ Ohi, __nv_bfloat16* __restrict__ Olo)
{
    extern __shared__ char smc[];
    uint32_t sb = smem_u32(smc);

    int tid = threadIdx.x;
    int wid = tid >> 5, lane = tid & 31;
    int wm = wid & 3, wn = wid >> 2;
    int bm = blockIdx.y * 128, bn = blockIdx.x * 128;

    const __nv_bfloat16* Abase_h = Ahi + (size_t)bm * K;
    const __nv_bfloat16* Abase_l = Alo + (size_t)bm * K;
    const __nv_bfloat16* Bbase_h = Bhi + (size_t)bn * K;
    const __nv_bfloat16* Bbase_l = Blo + (size_t)bn * K;

    int nchunk = K >> 5;

    int r0 = tid >> 2, seg0 = tid & 3;
    int r1 = r0 + 64;
    uint32_t s0 = (uint32_t)(r0 * 80 + seg0 * 16);
    uint32_t s1 = (uint32_t)(r1 * 80 + seg0 * 16);

    float acc[2][8][4];
    #pragma unroll
    for (int i = 0; i < 2; i++)
        #pragma unroll
        for (int j = 0; j < 8; j++)
            #pragma unroll
            for (int q = 0; q < 4; q++) acc[i][j][q] = 0.f;

    {
        uint32_t tb = sb;
        size_t g0 = (size_t)r0 * K + seg0 * 8;
        size_t g1 = (size_t)r1 * K + seg0 * 8;
        cp16(tb +         s0, Abase_h + g0); cp16(tb +         s1, Abase_h + g1);
        cp16(tb + 10240 + s0, Abase_l + g0); cp16(tb + 10240 + s1, Abase_l + g1);
        cp16(tb + 20480 + s0, Bbase_h + g0); cp16(tb + 20480 + s1, Bbase_h + g1);
        cp16(tb + 30720 + s0, Bbase_l + g0); cp16(tb + 30720 + s1, Bbase_l + g1);
        cp_commit();
    }

    int a_row = wm * 32 + (lane & 15);
    int a_colx = (lane >> 4) * 8;
    int b_row = wn * 64 + (lane & 7) + ((lane >> 4) * 8);
    int b_colx = ((lane >> 3) & 1) * 8;

    for (int c = 0; c < nchunk; c++) {
        asm volatile("cp.async.wait_group 0;" ::: "memory");
        __syncthreads();

        uint32_t tb = sb + (c & 1) * TGB;

        uint32_t ah[2][4], al[2][4];
        #pragma unroll
        for (int ma = 0; ma < 2; ma++) {
            uint32_t ad = tb + (uint32_t)((a_row + ma*16) * 80 + a_colx * 2);
            ldm_x4(ah[ma][0], ah[ma][1], ah[ma][2], ah[ma][3], ad);
            ldm_x4(al[ma][0], al[ma][1], al[ma][2], al[ma][3], ad + 10240);
        }
        {
            uint32_t bh[8][2];
            #pragma unroll
            for (int na2 = 0; na2 < 4; na2++) {
                uint32_t bd = tb + 20480 +
                    (uint32_t)((b_row + na2*16) * 80 + b_colx * 2);
                ldm_x4(bh[2*na2][0], bh[2*na2][1], bh[2*na2+1][0], bh[2*na2+1][1], bd);
            }
            #pragma unroll
            for (int ma = 0; ma < 2; ma++)
                #pragma unroll
                for (int na = 0; na < 8; na++)
                    mma_bf16(acc[ma][na], ah[ma], bh[na]);

            if (c + 1 < nchunk) {
                uint32_t pb = sb + ((c + 1) & 1) * TGB;
                int k0 = (c + 1) << 5;
                size_t g0 = (size_t)r0 * K + k0 + seg0 * 8;
                size_t g1 = (size_t)r1 * K + k0 + seg0 * 8;
                cp16(pb +         s0, Abase_h + g0); cp16(pb +         s1, Abase_h + g1);
                cp16(pb + 10240 + s0, Abase_l + g0); cp16(pb + 10240 + s1, Abase_l + g1);
                cp16(pb + 20480 + s0, Bbase_h + g0); cp16(pb + 20480 + s1, Bbase_h + g1);
                cp16(pb + 30720 + s0, Bbase_l + g0); cp16(pb + 30720 + s1, Bbase_l + g1);
                cp_commit();
            }

            #pragma unroll
            for (int ma = 0; ma < 2; ma++)
                #pragma unroll
                for (int na = 0; na < 8; na++)
                    mma_bf16(acc[ma][na], al[ma], bh[na]);
        }
        {
            uint32_t bl[8][2];
            #pragma unroll
            for (int na2 = 0; na2 < 4; na2++) {
                uint32_t bd = tb + 30720 +
                    (uint32_t)((b_row + na2*16) * 80 + b_colx * 2);
                ldm_x4(bl[2*na2][0], bl[2*na2][1], bl[2*na2+1][0], bl[2*na2+1][1], bd);
            }
            #pragma unroll
            for (int ma = 0; ma < 2; ma++)
                #pragma unroll
                for (int na = 0; na < 8; na++)
                    mma_bf16(acc[ma][na], ah[ma], bl[na]);
        }
        {
            int k = 16;
            #pragma unroll
            for (int ma = 0; ma < 2; ma++) {
                uint32_t ad = tb + (uint32_t)((a_row + ma*16) * 80 + (k + a_colx) * 2);
                ldm_x4(ah[ma][0], ah[ma][1], ah[ma][2], ah[ma][3], ad);
                ldm_x4(al[ma][0], al[ma][1], al[ma][2], al[ma][3], ad + 10240);
            }
            {
                uint32_t bh[8][2];
                #pragma unroll
                for (int na2 = 0; na2 < 4; na2++) {
                    uint32_t bd = tb + 20480 +
                        (uint32_t)((b_row + na2*16) * 80 + (k + b_colx) * 2);
                    ldm_x4(bh[2*na2][0], bh[2*na2][1], bh[2*na2+1][0], bh[2*na2+1][1], bd);
                }
                #pragma unroll
                for (int ma = 0; ma < 2; ma++)
                    #pragma unroll
                    for (int na = 0; na < 8; na++)
                        mma_bf16(acc[ma][na], ah[ma], bh[na]);
                #pragma unroll
                for (int ma = 0; ma < 2; ma++)
                    #pragma unroll
                    for (int na = 0; na < 8; na++)
                        mma_bf16(acc[ma][na], al[ma], bh[na]);
            }
            {
                uint32_t bl[8][2];
                #pragma unroll
                for (int na2 = 0; na2 < 4; na2++) {
                    uint32_t bd = tb + 30720 +
                        (uint32_t)((b_row + na2*16) * 80 + (k + b_colx) * 2);
                    ldm_x4(bl[2*na2][0], bl[2*na2][1], bl[2*na2+1][0], bl[2*na2+1][1], bd);
                }
                #pragma unroll
                for (int ma = 0; ma < 2; ma++)
                    #pragma unroll
                    for (int na = 0; na < 8; na++)
                        mma_bf16(acc[ma][na], ah[ma], bl[na]);
            }
        }
    }

    int gid = lane >> 2, tig = lane & 3;
    #pragma unroll
    for (int ma = 0; ma < 2; ma++) {
        #pragma unroll
        for (int half = 0; half < 2; half++) {
            int row = bm + wm*32 + ma*16 + gid + half*8;
            int colb = bn + wn*64;
            #pragma unroll
            for (int na = 0; na < 8; na++) {
                int cc = na*8 + tig*2;
                float v0 = acc[ma][na][half*2 + 0];
                float v1 = acc[ma][na][half*2 + 1];
                if (EPI == 0) {
                    *(float2*)(C + (size_t)row * N + colb + cc) = make_float2(v0, v1);
                } else if (EPI == 1) {
                    const float* rp = res + (size_t)row * N + colb;
                    v0 += bias[colb + cc]     + rp[cc];
                    v1 += bias[colb + cc + 1] + rp[cc + 1];
                    *(float2*)(C + (size_t)row * N + colb + cc) = make_float2(v0, v1);
                } else {
                    float u0 = v0 + bias[colb + cc];
                    float u1 = v1 + bias[colb + cc + 1];
                    v0 = 0.5f * u0 * (1.f + erff(u0 * 0.70710678118654752f));
                    v1 = 0.5f * u1 * (1.f + erff(u1 * 0.70710678118654752f));
                    __nv_bfloat16 h0, l0, h1, l1;
                    split_bf16(v0, h0, l0);
                    split_bf16(v1, h1, l1);
                    size_t oi = ((size_t)row * N + colb + cc) >> 1;
                    ((__nv_bfloat162*)Ohi)[oi] = __halves2bfloat162(h0, h1);
                    ((__nv_bfloat162*)Olo)[oi] = __halves2bfloat162(l0, l1);
                }
            }
        }
    }
}

// ---------------- LayerNorm (warp-per-row) ----------------
__global__ __launch_bounds__(256) void ln_split(const float* __restrict__ x,
    const float* __restrict__ w, const float* __restrict__ b,
    __nv_bfloat16* __restrict__ ohi, __nv_bfloat16* __restrict__ olo)
{
    int warp = threadIdx.x >> 5, lane = threadIdx.x & 31;
    int row = blockIdx.x * 8 + warp;
    const float* xr = x + (size_t)row * DIMN;

    float4 v[6];
    #pragma unroll
    for (int i = 0; i < 6; i++)
        v[i] = *(const float4*)(xr + (i*32 + lane)*4);

    float s = 0.f;
    #pragma unroll
    for (int i = 0; i < 6; i++) s += (v[i].x + v[i].y) + (v[i].z + v[i].w);
    #pragma unroll
    for (int o = 16; o; o >>= 1) s += __shfl_xor_sync(0xffffffffu, s, o);
    float mean = s * (1.f/768.f);

    float vs = 0.f;
    #pragma unroll
    for (int i = 0; i < 6; i++) {
        float d0 = v[i].x - mean, d1 = v[i].y - mean;
        float d2 = v[i].z - mean, d3 = v[i].w - mean;
        vs += (d0*d0 + d1*d1) + (d2*d2 + d3*d3);
    }
    #pragma unroll
    for (int o = 16; o; o >>= 1) vs += __shfl_xor_sync(0xffffffffu, vs, o);
    float rs = rsqrtf(vs * (1.f/768.f) + 1e-5f);

    size_t ob = (size_t)row * DIMN;
    #pragma unroll
    for (int i = 0; i < 6; i++) {
        int col = (i*32 + lane)*4;
        float4 w4 = *(const float4*)(w + col);
        float4 b4 = *(const float4*)(b + col);
        float r0 = (v[i].x - mean) * rs * w4.x + b4.x;
        float r1 = (v[i].y - mean) * rs * w4.y + b4.y;
        float r2 = (v[i].z - mean) * rs * w4.z + b4.z;
        float r3 = (v[i].w - mean) * rs * w4.w + b4.w;
        __nv_bfloat16 h0, l0, h1, l1, h2, l2, h3, l3;
        split_bf16(r0, h0, l0); split_bf16(r1, h1, l1);
        split_bf16(r2, h2, l2); split_bf16(r3, h3, l3);
        size_t oi = (ob + col) >> 1;
        ((__nv_bfloat162*)ohi)[oi]   = __halves2bfloat162(h0, h1);
        ((__nv_bfloat162*)ohi)[oi+1] = __halves2bfloat162(h2, h3);
        ((__nv_bfloat162*)olo)[oi]   = __halves2bfloat162(l0, l1);
        ((__nv_bfloat162*)olo)[oi+1] = __halves2bfloat162(l2, l3);
    }
}

// ---------------- fused attention: 25 warps; t=6 guard split out ----------
#define KSTR 68
#define AWRP 25
#define ATHR (AWRP*32)
#define ATT_SMEM ((SEQ*KSTR*2 + AWRP*4*64 + AWRP*4*224) * 4)

__global__ __launch_bounds__(ATHR) void attn_kernel(
    const float* __restrict__ QKV,
    __nv_bfloat16* __restrict__ Ohi, __nv_bfloat16* __restrict__ Olo)
{
    extern __shared__ float sm[];
    float* Ks = sm;
    float* Vs = Ks + SEQ*KSTR;
    float* qs = Vs + SEQ*KSTR;
    float* Ps = qs + AWRP*4*64;

    int bh = blockIdx.x;
    int bN = (bh / NHEAD) * SEQ;
    int h  = bh % NHEAD;
    size_t qbase = (size_t)bN * QKVN + h * DHEAD;

    for (int idx = threadIdx.x; idx < SEQ * DHEAD; idx += ATHR) {
        int r = idx >> 6, c = idx & 63;
        Ks[r*KSTR + c] = QKV[qbase + (size_t)r * QKVN + 768 + c];
        Vs[r*KSTR + c] = QKV[qbase + (size_t)r * QKVN + 1536 + c];
    }
    __syncthreads();

    int warp = threadIdx.x >> 5, lane = threadIdx.x & 31;
    float* qw = qs + warp * 256;
    float* pw = Ps + warp * 896;
    bool tail = (lane < SEQ - 192);   // lane < 4: j = lane+192 valid

    for (int g = warp; g < 49; g += AWRP) {
        int r0 = g * 4;
        for (int i = lane; i < 256; i += 32) {
            int rr = i >> 6, d = i & 63;
            qw[rr*64 + d] = QKV[qbase + (size_t)(r0 + rr) * QKVN + d];
        }
        __syncwarp();

        float s[4][7];
        #pragma unroll
        for (int r = 0; r < 4; r++)
            #pragma unroll
            for (int t = 0; t < 7; t++) s[r][t] = 0.f;

        #pragma unroll
        for (int d4 = 0; d4 < 16; d4++) {
            float4 q0 = *(float4*)(qw + 0*64 + d4*4);
            float4 q1 = *(float4*)(qw + 1*64 + d4*4);
            float4 q2 = *(float4*)(qw + 2*64 + d4*4);
            float4 q3 = *(float4*)(qw + 3*64 + d4*4);
            // t = 0..5: j = lane + 32t <= 191 < SEQ, no guard
            #pragma unroll
            for (int t = 0; t < 6; t++) {
                int j = lane + 32*t;
                float4 k4 = *(float4*)(Ks + j*KSTR + d4*4);
                s[0][t] += q0.x*k4.x + q0.y*k4.y + q0.z*k4.z + q0.w*k4.w;
                s[1][t] += q1.x*k4.x + q1.y*k4.y + q1.z*k4.z + q1.w*k4.w;
                s[2][t] += q2.x*k4.x + q2.y*k4.y + q2.z*k4.z + q2.w*k4.w;
                s[3][t] += q3.x*k4.x + q3.y*k4.y + q3.z*k4.z + q3.w*k4.w;
            }
            // t = 6: guarded
            if (tail) {
                int j = lane + 192;
                float4 k4 = *(float4*)(Ks + j*KSTR + d4*4);
                s[0][6] += q0.x*k4.x + q0.y*k4.y + q0.z*k4.z + q0.w*k4.w;
                s[1][6] += q1.x*k4.x + q1.y*k4.y + q1.z*k4.z + q1.w*k4.w;
                s[2][6] += q2.x*k4.x + q2.y*k4.y + q2.z*k4.z + q2.w*k4.w;
                s[3][6] += q3.x*k4.x + q3.y*k4.y + q3.z*k4.z + q3.w*k4.w;
            }
        }

        #pragma unroll
        for (int r = 0; r < 4; r++) {
            float m = -1e30f;
            #pragma unroll
            for (int t = 0; t < 6; t++) {
                float val = s[r][t] * 0.125f;
                s[r][t] = val;
                m = fmaxf(m, val);
            }
            {
                float val = tail ? s[r][6] * 0.125f : -1e30f;
                s[r][6] = val;
                m = fmaxf(m, val);
            }
            #pragma unroll
            for (int o = 16; o; o >>= 1) m = fmaxf(m, __shfl_xor_sync(0xffffffffu, m, o));
            float sum = 0.f;
            #pragma unroll
            for (int t = 0; t < 6; t++) {
                float e = __expf(s[r][t] - m);
                s[r][t] = e;
                sum += e;
            }
            {
                float e = tail ? __expf(s[r][6] - m) : 0.f;
                s[r][6] = e;
                sum += e;
            }
            #pragma unroll
            for (int o = 16; o; o >>= 1) sum += __shfl_xor_sync(0xffffffffu, sum, o);
            float inv = 1.f / sum;
            #pragma unroll
            for (int t = 0; t < 6; t++)
                pw[r*224 + lane + 32*t] = s[r][t] * inv;
            if (tail)
                pw[r*224 + lane + 192] = s[r][6] * inv;
        }
        __syncwarp();

        float2 o0 = make_float2(0.f,0.f), o1 = o0, o2 = o0, o3 = o0;
        for (int jj = 0; jj < 49; jj++) {
            int j = jj * 4;
            float4 p0 = *(float4*)(pw + 0*224 + j);
            float4 p1 = *(float4*)(pw + 1*224 + j);
            float4 p2 = *(float4*)(pw + 2*224 + j);
            float4 p3 = *(float4*)(pw + 3*224 + j);
            float2 va = *(float2*)(Vs + (j+0)*KSTR + lane*2);
            float2 vb = *(float2*)(Vs + (j+1)*KSTR + lane*2);
            float2 vc = *(float2*)(Vs + (j+2)*KSTR + lane*2);
            float2 vd = *(float2*)(Vs + (j+3)*KSTR + lane*2);
            o0.x += p0.x*va.x; o0.y += p0.x*va.y;
            o0.x += p0.y*vb.x; o0.y += p0.y*vb.y;
            o0.x += p0.z*vc.x; o0.y += p0.z*vc.y;
            o0.x += p0.w*vd.x; o0.y += p0.w*vd.y;
            o1.x += p1.x*va.x; o1.y += p1.x*va.y;
            o1.x += p1.y*vb.x; o1.y += p1.y*vb.y;
            o1.x += p1.z*vc.x; o1.y += p1.z*vc.y;
            o1.x += p1.w*vd.x; o1.y += p1.w*vd.y;
            o2.x += p2.x*va.x; o2.y += p2.x*va.y;
            o2.x += p2.y*vb.x; o2.y += p2.y*vb.y;
            o2.x += p2.z*vc.x; o2.y += p2.z*vc.y;
            o2.x += p2.w*vd.x; o2.y += p2.w*vd.y;
            o3.x += p3.x*va.x; o3.y += p3.x*va.y;
            o3.x += p3.y*vb.x; o3.y += p3.y*vb.y;
            o3.x += p3.z*vc.x; o3.y += p3.z*vc.y;
            o3.x += p3.w*vd.x; o3.y += p3.w*vd.y;
        }
        #pragma unroll
        for (int r = 0; r < 4; r++) {
            float2 ov = (r == 0) ? o0 : (r == 1) ? o1 : (r == 2) ? o2 : o3;
            __nv_bfloat16 h0, l0, h1, l1;
            split_bf16(ov.x, h0, l0);
            split_bf16(ov.y, h1, l1);
            size_t oi = ((size_t)(bN + r0 + r) * DIMN + h * DHEAD + lane*2) >> 1;
            ((__nv_bfloat162*)Ohi)[oi] = __halves2bfloat162(h0, h1);
            ((__nv_bfloat162*)Olo)[oi] = __halves2bfloat162(l0, l1);
        }
        __syncwarp();
    }
}

// ---------------- k-means ----------------
__global__ __launch_bounds__(256) void assign_kernel(
    const float* __restrict__ X, const float* __restrict__ C,
    int* __restrict__ labels, int* __restrict__ cntp)
{
    __shared__ float Xs[64*65];
    __shared__ float Cs[64*65];
    __shared__ float cred[256];
    __shared__ float cnsh[64];
    __shared__ int   hist[64];
    int p0 = blockIdx.x * 64;
    int tid = threadIdx.x;

    {
        int row = tid & 63, q = tid >> 6;
        const float* cr = C + (size_t)row * DIMN + q * 192;
        float s = 0.f;
        #pragma unroll 4
        for (int k = 0; k < 192; k++) s += cr[k] * cr[k];
        cred[(q << 6) | row] = s;
    }
    if (tid < 64) hist[tid] = 0;
    __syncthreads();
    if (tid < 64)
        cnsh[tid] = (cred[tid] + cred[64 + tid]) + (cred[128 + tid] + cred[192 + tid]);

    int ty = tid >> 4, tx = tid & 15;
    float acc[4][4];
    #pragma unroll
    for (int i = 0; i < 4; i++)
        #pragma unroll
        for (int j = 0; j < 4; j++) acc[i][j] = 0.f;

    for (int k0 = 0; k0 < DIMN; k0 += 64) {
        __syncthreads();
        for (int idx = tid; idx < 4096; idx += 256) {
            int r = idx >> 6, d = idx & 63;
            Xs[r*65 + d] = X[(size_t)(p0 + r) * DIMN + k0 + d];
            Cs[r*65 + d] = C[(size_t)r * DIMN + k0 + d];
        }
        __syncthreads();
        for (int k = 0; k < 64; k++) {
            float a[4], b[4];
            #pragma unroll
            for (int i = 0; i < 4; i++) a[i] = Xs[(ty*4 + i)*65 + k];
            #pragma unroll
            for (int j = 0; j < 4; j++) b[j] = Cs[(tx*4 + j)*65 + k];
            #pragma unroll
            for (int i = 0; i < 4; i++)
                #pragma unroll
                for (int j = 0; j < 4; j++) acc[i][j] += a[i] * b[j];
        }
    }
    __syncthreads();
    #pragma unroll
    for (int i = 0; i < 4; i++)
        #pragma unroll
        for (int j = 0; j < 4; j++)
            Xs[(ty*4 + i)*64 + tx*4 + j] = cnsh[tx*4 + j] - 2.f * acc[i][j];
    __syncthreads();
    if (tid < 64) {
        int p = tid;
        float best = Xs[p*64]; int bi = 0;
        for (int c = 1; c < 64; c++) {
            float d = Xs[p*64 + c];
            if (d < best) { best = d; bi = c; }
        }
        labels[p0 + p] = bi;
        atomicAdd(&hist[bi], 1);
    }
    __syncthreads();
    if (tid < 64) cntp[blockIdx.x * 64 + tid] = hist[tid];
}

__global__ __launch_bounds__(768) void kmeans_partial(
    const float* __restrict__ X, const int* __restrict__ labels,
    float* __restrict__ partials)
{
    extern __shared__ float sacc[];
    for (int i = threadIdx.x; i < KCENT*DIMN; i += 768) sacc[i] = 0.f;
    __syncthreads();
    int p0 = blockIdx.x * (TOK/NPART);
    int t = threadIdx.x;
    for (int p = p0; p < p0 + (TOK/NPART); p++) {
        int l = labels[p];
        sacc[l * DIMN + t] += X[(size_t)p * DIMN + t];
    }
    __syncthreads();
    float* out = partials + (size_t)blockIdx.x * (KCENT*DIMN);
    for (int i = threadIdx.x; i < KCENT*DIMN; i += 768) out[i] = sacc[i];
}

__global__ __launch_bounds__(256) void kmeans_reduce(
    const float* __restrict__ partials, const int* __restrict__ cntp,
    float* __restrict__ centers)
{
    __shared__ float s_cnt;
    int idx = blockIdx.x * 256 + threadIdx.x;
    int row = idx / DIMN;
    if (threadIdx.x == 0) {
        int c = 0;
        for (int b = 0; b < NASS; b++) c += cntp[b * 64 + row];
        s_cnt = (float)c;
    }
    __syncthreads();
    float s = 0.f;
    #pragma unroll 4
    for (int b = 0; b < NPART; b++) s += partials[(size_t)b * (KCENT*DIMN) + idx];
    if (s_cnt > 0.f) centers[idx] = s / s_cnt;
}

__global__ __launch_bounds__(256) void cproj_kernel(
    const float* __restrict__ centers, const float* __restrict__ W,
    const float* __restrict__ bias, float* __restrict__ out)
{
    int idx = blockIdx.x * 256 + threadIdx.x;
    if (idx >= KCENT*DIMN) return;
    int r = idx / DIMN, c = idx - r * DIMN;
    const float* cr = centers + (size_t)r * DIMN;
    float acc = 0.f;
    #pragma unroll 4
    for (int k = 0; k < DIMN; k++) acc += cr[k] * W[(size_t)k * DIMN + c];
    out[idx] = acc + bias[c];
}

__global__ __launch_bounds__(256) void gather_kernel(
    const float* __restrict__ cproj, const int* __restrict__ labels,
    float* __restrict__ out)
{
    int idx = blockIdx.x * 256 + threadIdx.x;
    if (idx >= TOK*DIMN) return;
    int p = idx / DIMN, d = idx - p * DIMN;
    out[idx] = cproj[(size_t)labels[p] * DIMN + d];
}

// ---------------- host orchestration ----------------
extern "C" void kernel_launch(void* const* d_in, const int* in_sizes, int n_in,
                              void* d_out, int out_size)
{
    const float* in_x   = (const float*)d_in[0];
    const float* ln1_w  = (const float*)d_in[1];
    const float* ln1_b  = (const float*)d_in[2];
    const float* wq     = (const float*)d_in[3];
    const float* wk     = (const float*)d_in[4];
    const float* wv     = (const float*)d_in[5];
    const float* wo     = (const float*)d_in[6];
    const float* bo     = (const float*)d_in[7];
    const float* ln2_w  = (const float*)d_in[8];
    const float* ln2_b  = (const float*)d_in[9];
    const float* w1     = (const float*)d_in[10];
    const float* b1     = (const float*)d_in[11];
    const float* w2     = (const float*)d_in[12];
    const float* b2     = (const float*)d_in[13];
    const float* ct_w   = (const float*)d_in[14];
    const float* ct_b   = (const float*)d_in[15];

    float *px, *pqkv, *pcent, *ppart, *pcproj;
    int *plab, *pcntp;
    __nv_bfloat16 *pah, *pal, *pgh, *pgl,
                  *pwqkvh, *pwqkvl, *pwoh, *pwol, *pw1h, *pw1l, *pw2h, *pw2l;
    cudaGetSymbolAddress((void**)&px,    g_x);
    cudaGetSymbolAddress((void**)&pqkv,  g_qkv);
    cudaGetSymbolAddress((void**)&pcent, g_centers);
    cudaGetSymbolAddress((void**)&plab,  g_labels);
    cudaGetSymbolAddress((void**)&pcntp, g_cntp);
    cudaGetSymbolAddress((void**)&ppart, g_part);
    cudaGetSymbolAddress((void**)&pcproj,g_cproj);
    cudaGetSymbolAddress((void**)&pah,   g_ah);
    cudaGetSymbolAddress((void**)&pal,   g_al);
    cudaGetSymbolAddress((void**)&pgh,   g_gh);
    cudaGetSymbolAddress((void**)&pgl,   g_gl);
    cudaGetSymbolAddress((void**)&pwqkvh,g_wqkvh);
    cudaGetSymbolAddress((void**)&pwqkvl,g_wqkvl);
    cudaGetSymbolAddress((void**)&pwoh,  g_woh);
    cudaGetSymbolAddress((void**)&pwol,  g_wol);
    cudaGetSymbolAddress((void**)&pw1h,  g_w1h);
    cudaGetSymbolAddress((void**)&pw1l,  g_w1l);
    cudaGetSymbolAddress((void**)&pw2h,  g_w2h);
    cudaGetSymbolAddress((void**)&pw2l,  g_w2l);

    cudaFuncSetAttribute(attn_kernel, cudaFuncAttributeMaxDynamicSharedMemorySize, ATT_SMEM);
    cudaFuncSetAttribute(kmeans_partial, cudaFuncAttributeMaxDynamicSharedMemorySize,
                         KCENT*DIMN*(int)sizeof(float));
    cudaFuncSetAttribute(tgemm<0>, cudaFuncAttributeMaxDynamicSharedMemorySize, TG_SMEM);
    cudaFuncSetAttribute(tgemm<1>, cudaFuncAttributeMaxDynamicSharedMemorySize, TG_SMEM);
    cudaFuncSetAttribute(tgemm<2>, cudaFuncAttributeMaxDynamicSharedMemorySize, TG_SMEM);

    dim3 gQKV(QKVN/128, TOK/128);
    dim3 g768(DIMN/128, TOK/128);
    dim3 g3072(MLPN/128, TOK/128);

    // index 3 = attn_kernel (profiled)
    conv_sq<<<dim3(DIMN/32, DIMN/32, DEPTH*4), 256>>>(wq, wk, wv, wo,
        pwqkvh, pwqkvl, pwoh, pwol);                                                // 0
    ln_split<<<TOK/8, 256>>>(in_x, ln1_w, ln1_b, pah, pal);                         // 1
    tgemm<0><<<gQKV, 256, TG_SMEM>>>(TOK, QKVN, DIMN, pah, pal,
        pwqkvh, pwqkvl, nullptr, nullptr, pqkv, nullptr, nullptr);                  // 2
    attn_kernel<<<32*NHEAD, ATHR, ATT_SMEM>>>(pqkv, pah, pal);                      // 3 <- profiled
    copy_kernel<<<(TOK*DIMN/4 + 255)/256, 256>>>((const float4*)in_x, (float4*)px,
                                                 TOK*DIMN/4);                       // 4
    conv_w1<<<dim3(MLPN/32, DIMN/32, DEPTH), 256>>>(w1, pw1h, pw1l);                // 5
    conv_w2<<<dim3(DIMN/32, MLPN/32, DEPTH), 256>>>(w2, pw2h, pw2l);                // 6

    for (int d = 0; d < DEPTH; d++) {
        size_t oq  = (size_t)d*QKVN*DIMN;
        size_t osq = (size_t)DIMN*DIMN;
        size_t om  = (size_t)d*DIMN*MLPN;

        if (d > 0) {
            ln_split<<<TOK/8, 256>>>(px, ln1_w + d*DIMN, ln1_b + d*DIMN, pah, pal);
            tgemm<0><<<gQKV, 256, TG_SMEM>>>(TOK, QKVN, DIMN, pah, pal,
                pwqkvh + oq, pwqkvl + oq, nullptr, nullptr, pqkv, nullptr, nullptr);
            attn_kernel<<<32*NHEAD, ATHR, ATT_SMEM>>>(pqkv, pah, pal);
        }
        tgemm<1><<<g768, 256, TG_SMEM>>>(TOK, DIMN, DIMN, pah, pal,
            pwoh + (size_t)d*osq, pwol + (size_t)d*osq, bo + d*DIMN, px, px,
            nullptr, nullptr);
        ln_split<<<TOK/8, 256>>>(px, ln2_w + d*DIMN, ln2_b + d*DIMN, pah, pal);
        tgemm<2><<<g3072, 256, TG_SMEM>>>(TOK, MLPN, DIMN, pah, pal,
            pw1h + om, pw1l + om, b1 + d*MLPN, nullptr, nullptr, pgh, pgl);
        tgemm<1><<<g768, 256, TG_SMEM>>>(TOK, DIMN, MLPN, pgh, pgl,
            pw2h + om, pw2l + om, b2 + d*DIMN, px, px, nullptr, nullptr);
    }

    // ---- k-means ----
    cudaMemcpyAsync(pcent, px, (size_t)KCENT*DIMN*sizeof(float), cudaMemcpyDeviceToDevice, 0);
    for (int it = 0; it < KMIT; it++) {
        assign_kernel<<<NASS, 256>>>(px, pcent, plab, pcntp);
        kmeans_partial<<<NPART, 768, KCENT*DIMN*sizeof(float)>>>(px, plab, ppart);
        kmeans_reduce<<<KCENT*DIMN/256, 256>>>(ppart, pcntp, pcent);
    }
    assign_kernel<<<NASS, 256>>>(px, pcent, plab, pcntp);

    cproj_kernel<<<(KCENT*DIMN + 255)/256, 256>>>(pcent, ct_w, ct_b, pcproj);
    gather_kernel<<<(TOK*DIMN + 255)/256, 256>>>(pcproj, plab, (float*)d_out);
}